// round 2
// baseline (speedup 1.0000x reference)
#include <cuda_runtime.h>

// Problem constants
#define BATCH 128
#define SEQLEN 8194
#define PL 8192          // conv output length (valid, k=3)
#define NCH 32           // conv channels
#define SEC 4            // PROT_SECTION
#define DDIM 128         // NCH*SEC
#define NL 2048          // PL/SEC
#define NTILE 128        // n columns per CTA in kernel 1
#define NT (NL / NTILE)  // 16 tiles
#define TPB 256

// scratch (2 MB total) — __device__ globals, no allocation at launch time
__device__ float g_e[BATCH * NL];
__device__ float g_w[BATCH * NL];

// ---------------------------------------------------------------------------
// Kernel 1: per (batch b, tile t) CTA
//   - embed + conv -> H tile [128 d x 128 n] in SMEM
//   - M = tanh(W_a @ Htile), e[n] = v_a . M[:,n]  -> g_e
// ---------------------------------------------------------------------------
__global__ __launch_bounds__(TPB, 1) void k1_conv_attn(
    const int* __restrict__ seq, const float* __restrict__ emb,
    const float* __restrict__ cw, const float* __restrict__ cb,
    const float* __restrict__ Wa, const float* __restrict__ va)
{
    extern __shared__ float sm[];
    float* sA   = sm;            // 16384  W_a[d][e] row-major
    float* sH   = sA + 16384;    // 16384  H[e][n]
    float* ep   = sH + 16384;    // 2048   partial e reduction [16][128]
    float* xs   = ep + 2048;     // 2600   embedded inputs [4 seg][130 pos][5]
    float* semb = xs + 2600;     // 130
    float* scw  = semb + 130;    // 480
    float* scb  = scw + 480;     // 32
    float* sv   = scb + 32;      // 128
    int*   sseq = (int*)(sv + 128); // 520 ints

    const int tid = threadIdx.x;
    const int t = blockIdx.x;   // n tile
    const int b = blockIdx.y;   // batch

    // small tables
    for (int i = tid; i < 130; i += TPB) semb[i] = emb[i];
    for (int i = tid; i < 480; i += TPB) scw[i] = cw[i];
    if (tid < 32)  scb[tid] = cb[tid];
    if (tid < 128) sv[tid] = va[tid];

    // W_a (vectorized)
    {
        const float4* W4 = (const float4*)Wa;
        float4* A4 = (float4*)sA;
        #pragma unroll
        for (int i = tid; i < 4096; i += TPB) A4[i] = W4[i];
    }

    // sequence slices: 4 sections x 130 positions
    for (int i = tid; i < 4 * 130; i += TPB) {
        int s = i / 130, j = i % 130;
        sseq[i] = seq[b * SEQLEN + s * NL + t * NTILE + j];
    }
    __syncthreads();

    // embedding lookup into xs[(s*130 + pos)*5 + i]
    for (int i = tid; i < 4 * 130 * 5; i += TPB) {
        int i5 = i % 5, j = i / 5;
        xs[i] = semb[sseq[j] * 5 + i5];
    }
    __syncthreads();

    // conv(5->32, k=3) + bias + relu -> sH[(c*4+s)*128 + n]
    for (int idx = tid; idx < DDIM * NTILE; idx += TPB) {
        int n = idx & 127;
        int c = (idx >> 7) & 31;
        int s = idx >> 12;
        const float* w = scw + c * 15;
        const float* xb = xs + (s * 130 + n) * 5;
        float acc = scb[c];
        #pragma unroll
        for (int k = 0; k < 3; k++)
            #pragma unroll
            for (int i2 = 0; i2 < 5; i2++)
                acc += xb[k * 5 + i2] * w[i2 * 3 + k];
        sH[(c * 4 + s) * NTILE + n] = fmaxf(acc, 0.f);
    }
    __syncthreads();

    // GEMM: M[d][n] = sum_e Wa[d][e] * H[e][n]; 8x8 register tile per thread
    const int tx = tid & 15, ty = tid >> 4;
    float acc[8][8];
    #pragma unroll
    for (int ii = 0; ii < 8; ii++)
        #pragma unroll
        for (int jj = 0; jj < 8; jj++) acc[ii][jj] = 0.f;

    #pragma unroll 4
    for (int k = 0; k < 128; k++) {
        float af[8], bf[8];
        #pragma unroll
        for (int ii = 0; ii < 8; ii++) af[ii] = sA[(ty + 16 * ii) * 128 + k];
        #pragma unroll
        for (int jj = 0; jj < 8; jj++) bf[jj] = sH[k * 128 + tx + 16 * jj];
        #pragma unroll
        for (int ii = 0; ii < 8; ii++)
            #pragma unroll
            for (int jj = 0; jj < 8; jj++)
                acc[ii][jj] += af[ii] * bf[jj];
    }

    // e partials: sum_d v[d] * tanh(M[d][n]) over this thread's 8 d's
    #pragma unroll
    for (int jj = 0; jj < 8; jj++) {
        float ssum = 0.f;
        #pragma unroll
        for (int ii = 0; ii < 8; ii++) {
            int d = ty + 16 * ii;
            ssum += sv[d] * tanhf(acc[ii][jj]);
        }
        ep[ty * 128 + tx + 16 * jj] = ssum;
    }
    __syncthreads();
    // reduce 16 ty-groups
    for (int off = 8; off > 0; off >>= 1) {
        if (ty < off) {
            #pragma unroll
            for (int jj = 0; jj < 8; jj++)
                ep[ty * 128 + tx + 16 * jj] += ep[(ty + off) * 128 + tx + 16 * jj];
        }
        __syncthreads();
    }
    if (ty == 0) {
        #pragma unroll
        for (int jj = 0; jj < 8; jj++)
            g_e[b * NL + t * NTILE + tx + 16 * jj] = ep[tx + 16 * jj];
    }
}

// ---------------------------------------------------------------------------
// Kernel 2: stable softmax over n per batch -> g_w
// ---------------------------------------------------------------------------
__global__ __launch_bounds__(TPB) void k2_softmax()
{
    __shared__ float red[TPB];
    const int b = blockIdx.x, tid = threadIdx.x;
    float vals[8];
    float vmax = -1e30f;
    #pragma unroll
    for (int j = 0; j < 8; j++) {
        vals[j] = g_e[b * NL + tid + TPB * j];
        vmax = fmaxf(vmax, vals[j]);
    }
    red[tid] = vmax; __syncthreads();
    for (int off = 128; off > 0; off >>= 1) {
        if (tid < off) red[tid] = fmaxf(red[tid], red[tid + off]);
        __syncthreads();
    }
    vmax = red[0]; __syncthreads();

    float ssum = 0.f;
    #pragma unroll
    for (int j = 0; j < 8; j++) { vals[j] = expf(vals[j] - vmax); ssum += vals[j]; }
    red[tid] = ssum; __syncthreads();
    for (int off = 128; off > 0; off >>= 1) {
        if (tid < off) red[tid] += red[tid + off];
        __syncthreads();
    }
    float inv = 1.f / red[0];
    #pragma unroll
    for (int j = 0; j < 8; j++) g_w[b * NL + tid + TPB * j] = vals[j] * inv;
}

// ---------------------------------------------------------------------------
// Kernel 3: per (section s, batch b) CTA: recompute conv over the section,
// weighted-sum with w -> ctx[b*128 + c*4 + s]
// ---------------------------------------------------------------------------
__global__ __launch_bounds__(TPB, 2) void k3_ctx(
    const int* __restrict__ seq, const float* __restrict__ emb,
    const float* __restrict__ cw, const float* __restrict__ cb,
    float* __restrict__ out)
{
    extern __shared__ float sm[];
    float* xs   = sm;            // 2050*5 = 10250
    float* scw  = xs + 10250;    // 480
    float* scb  = scw + 480;     // 32
    float* semb = scb + 32;      // 130
    float* wsum = semb + 130;    // 8 warps * 32 ch = 256
    int*   sseq = (int*)(wsum + 256); // 2050 ints

    const int tid = threadIdx.x;
    const int s = blockIdx.x;    // section 0..3
    const int b = blockIdx.y;

    for (int i = tid; i < 130; i += TPB) semb[i] = emb[i];
    for (int i = tid; i < 480; i += TPB) scw[i] = cw[i];
    if (tid < 32) scb[tid] = cb[tid];
    for (int i = tid; i < 2050; i += TPB)
        sseq[i] = seq[b * SEQLEN + s * NL + i];
    __syncthreads();
    for (int i = tid; i < 2050 * 5; i += TPB) {
        int i5 = i % 5, j = i / 5;
        xs[i] = semb[sseq[j] * 5 + i5];
    }
    __syncthreads();

    float acc[NCH];
    #pragma unroll
    for (int c = 0; c < NCH; c++) acc[c] = 0.f;

    for (int m = 0; m < NL / TPB; m++) {
        int n = tid + m * TPB;
        float wv = g_w[b * NL + n];
        float xv[15];
        const float* xb = xs + n * 5;
        #pragma unroll
        for (int q = 0; q < 15; q++) xv[q] = xb[q];
        #pragma unroll
        for (int c = 0; c < NCH; c++) {
            const float* w = scw + c * 15;
            float z = scb[c];
            #pragma unroll
            for (int k = 0; k < 3; k++)
                #pragma unroll
                for (int i2 = 0; i2 < 5; i2++)
                    z += xv[k * 5 + i2] * w[i2 * 3 + k];
            acc[c] += wv * fmaxf(z, 0.f);
        }
    }

    // warp reduce each channel, then cross-warp via smem
    const int lane = tid & 31, warp = tid >> 5;
    #pragma unroll
    for (int c = 0; c < NCH; c++) {
        float v = acc[c];
        #pragma unroll
        for (int off = 16; off > 0; off >>= 1)
            v += __shfl_down_sync(0xffffffffu, v, off);
        if (lane == 0) wsum[warp * 32 + c] = v;
    }
    __syncthreads();
    if (tid < 32) {
        float v = 0.f;
        #pragma unroll
        for (int wp = 0; wp < 8; wp++) v += wsum[wp * 32 + tid];
        out[b * DDIM + tid * 4 + s] = v;
    }
}

// ---------------------------------------------------------------------------
extern "C" void kernel_launch(void* const* d_in, const int* in_sizes, int n_in,
                              void* d_out, int out_size)
{
    const int*   seq = (const int*)d_in[0];
    const float* emb = (const float*)d_in[1];
    const float* cw  = (const float*)d_in[2];
    const float* cb  = (const float*)d_in[3];
    const float* Wa  = (const float*)d_in[4];
    const float* va  = (const float*)d_in[5];
    float* out = (float*)d_out;

    const int sm1 = (16384 + 16384 + 2048 + 2600 + 130 + 480 + 32 + 128) * 4 + 520 * 4;
    const int sm3 = (10250 + 480 + 32 + 130 + 256) * 4 + 2050 * 4;
    cudaFuncSetAttribute(k1_conv_attn, cudaFuncAttributeMaxDynamicSharedMemorySize, sm1);
    cudaFuncSetAttribute(k3_ctx,       cudaFuncAttributeMaxDynamicSharedMemorySize, sm3);

    k1_conv_attn<<<dim3(NT, BATCH), TPB, sm1>>>(seq, emb, cw, cb, Wa, va);
    k2_softmax<<<BATCH, TPB>>>();
    k3_ctx<<<dim3(SEC, BATCH), TPB, sm3>>>(seq, emb, cw, cb, out);
}

// round 6
// speedup vs baseline: 2.2283x; 2.2283x over previous
#include <cuda_runtime.h>
#include <cuda_bf16.h>
#include <cstdint>

#define BATCH 128
#define SEQLEN 8194
#define NCH 32
#define SEC 4
#define DDIM 128
#define NL 2048
#define NTILE 128
#define NT (NL / NTILE)
#define TPB 256
#define PITCH 136   // bf16 elements per smem row (128 + 8 pad)

// scratch
__device__ float g_e[BATCH * NL];
__device__ float g_w[BATCH * NL];
__device__ float g_H[(size_t)BATCH * DDIM * NL];   // 134 MB fp32 H

// ---------------- helpers ----------------
__device__ __forceinline__ uint32_t smem_u32(const void* p) {
    uint32_t a;
    asm("{ .reg .u64 t; cvta.to.shared.u64 t, %1; cvt.u32.u64 %0, t; }" : "=r"(a) : "l"(p));
    return a;
}

#define LDSM_X4(r, addr) \
    asm volatile("ldmatrix.sync.aligned.m8n8.x4.shared.b16 {%0,%1,%2,%3}, [%4];" \
        : "=r"((r)[0]), "=r"((r)[1]), "=r"((r)[2]), "=r"((r)[3]) : "r"(addr))

#define LDSM_X4_T(r, addr) \
    asm volatile("ldmatrix.sync.aligned.m8n8.x4.trans.shared.b16 {%0,%1,%2,%3}, [%4];" \
        : "=r"((r)[0]), "=r"((r)[1]), "=r"((r)[2]), "=r"((r)[3]) : "r"(addr))

#define MMA_BF16(c, a, b0, b1) \
    asm volatile("mma.sync.aligned.m16n8k16.row.col.f32.bf16.bf16.f32 " \
        "{%0,%1,%2,%3}, {%4,%5,%6,%7}, {%8,%9}, {%0,%1,%2,%3};" \
        : "+f"((c)[0]), "+f"((c)[1]), "+f"((c)[2]), "+f"((c)[3]) \
        : "r"((a)[0]), "r"((a)[1]), "r"((a)[2]), "r"((a)[3]), "r"(b0), "r"(b1))

__device__ __forceinline__ float ftanh(float x) {
    float cx = fminf(fmaxf(x, -15.f), 15.f);
    float u = __expf(2.f * cx);
    return __fdividef(u - 1.f, u + 1.f);
}

// SMEM byte offsets (k1): A/B tiles are [128][PITCH] bf16 = 34816 B each
#define OFF_AHI 0
#define OFF_ALO 34816
#define OFF_BHI 69632
#define OFF_BLO 104448
#define OFF_XS   139264              // 2600 floats
#define OFF_SEMB (OFF_XS + 10400)    // 130 f
#define OFF_SCW  (OFF_SEMB + 520)    // 480 f
#define OFF_SCB  (OFF_SCW + 1920)    // 32 f
#define OFF_SV   (OFF_SCB + 128)     // 128 f
#define OFF_SSEQ (OFF_SV + 512)      // 520 i
#define OFF_EP2  (OFF_SSEQ + 2080)   // 2 x 128 f
#define SM1_BYTES (OFF_EP2 + 1024)

// ---------------------------------------------------------------------------
// Kernel 1: embed+conv -> H (gmem fp32 + smem bf16 hi/lo) -> HMMA GEMM -> e
// ---------------------------------------------------------------------------
__global__ __launch_bounds__(TPB, 1) void k1_conv_attn(
    const int* __restrict__ seq, const float* __restrict__ emb,
    const float* __restrict__ cw, const float* __restrict__ cb,
    const float* __restrict__ Wa, const float* __restrict__ va)
{
    extern __shared__ char sm[];
    const uint32_t smb = smem_u32(sm);
    float* semb = (float*)(sm + OFF_SEMB);
    float* scw  = (float*)(sm + OFF_SCW);
    float* scb  = (float*)(sm + OFF_SCB);
    float* sv   = (float*)(sm + OFF_SV);
    float* xs   = (float*)(sm + OFF_XS);
    int*   sseq = (int*)(sm + OFF_SSEQ);
    float* ep2  = (float*)(sm + OFF_EP2);

    const int tid = threadIdx.x;
    const int wid = tid >> 5, lane = tid & 31;
    const int t = blockIdx.x, b = blockIdx.y;

    // small tables
    for (int i = tid; i < 130; i += TPB) semb[i] = emb[i];
    for (int i = tid; i < 480; i += TPB) scw[i] = cw[i];
    if (tid < 32)  scb[tid] = cb[tid];
    if (tid < 128) sv[tid] = va[tid];
    for (int i = tid; i < 4 * 130; i += TPB) {
        int s = i / 130, j = i % 130;
        sseq[i] = seq[b * SEQLEN + s * NL + t * NTILE + j];
    }

    // W_a -> bf16 hi/lo A tiles, row-major [d][e], pitch PITCH
    {
        const float2* W2 = (const float2*)Wa;
        #pragma unroll
        for (int i = tid; i < 8192; i += TPB) {
            float2 v = W2[i];
            int d = i >> 6, e2 = (i & 63) << 1;
            __nv_bfloat16 h0 = __float2bfloat16(v.x);
            __nv_bfloat16 h1 = __float2bfloat16(v.y);
            __nv_bfloat16 l0 = __float2bfloat16(v.x - __bfloat162float(h0));
            __nv_bfloat16 l1 = __float2bfloat16(v.y - __bfloat162float(h1));
            uint32_t o = (uint32_t)(d * PITCH + e2) * 2;
            *(__nv_bfloat162*)(sm + OFF_AHI + o) = __nv_bfloat162(h0, h1);
            *(__nv_bfloat162*)(sm + OFF_ALO + o) = __nv_bfloat162(l0, l1);
        }
    }
    __syncthreads();

    // embedding
    for (int i = tid; i < 4 * 130 * 5; i += TPB) {
        int i5 = i % 5, j = i / 5;
        xs[i] = semb[sseq[j] * 5 + i5];
    }
    __syncthreads();

    // conv + relu -> g_H (fp32, coalesced in n) + B tiles [e][n] bf16 hi/lo
    for (int idx = tid; idx < DDIM * NTILE; idx += TPB) {
        int n = idx & 127;
        int c = (idx >> 7) & 31;
        int s = idx >> 12;
        int e = c * 4 + s;
        const float* w = scw + c * 15;
        const float* xb = xs + (s * 130 + n) * 5;
        float acc = scb[c];
        #pragma unroll
        for (int k = 0; k < 3; k++)
            #pragma unroll
            for (int i2 = 0; i2 < 5; i2++)
                acc += xb[k * 5 + i2] * w[i2 * 3 + k];
        acc = fmaxf(acc, 0.f);
        g_H[(size_t)(b * DDIM + e) * NL + t * NTILE + n] = acc;
        __nv_bfloat16 hi = __float2bfloat16(acc);
        __nv_bfloat16 lo = __float2bfloat16(acc - __bfloat162float(hi));
        uint32_t o = (uint32_t)(e * PITCH + n) * 2;
        *(__nv_bfloat16*)(sm + OFF_BHI + o) = hi;
        *(__nv_bfloat16*)(sm + OFF_BLO + o) = lo;
    }
    __syncthreads();

    // ---------------- GEMM: M[d][n] = Wa @ H, bf16 hi/lo x3, fp32 accum ----
    // warp layout: 2 (m) x 4 (n); warp tile 64(m) x 32(n)
    const int wm = (wid & 1) * 64;
    const int wn = (wid >> 1) * 32;
    const int qd = lane >> 3, r8 = lane & 7;  // ldmatrix quad / row

    float c[4][4][4];
    #pragma unroll
    for (int mt = 0; mt < 4; mt++)
        #pragma unroll
        for (int nt = 0; nt < 4; nt++)
            #pragma unroll
            for (int q = 0; q < 4; q++) c[mt][nt][q] = 0.f;

    #pragma unroll
    for (int ks = 0; ks < 8; ks++) {
        const int k0 = ks * 16;
        uint32_t ahi[4][4], alo[4][4];
        #pragma unroll
        for (int mt = 0; mt < 4; mt++) {
            uint32_t addr = smb + OFF_AHI +
                (uint32_t)((wm + mt * 16 + r8 + (qd & 1) * 8) * PITCH + k0 + (qd >> 1) * 8) * 2;
            LDSM_X4(ahi[mt], addr);
            LDSM_X4(alo[mt], addr + (OFF_ALO - OFF_AHI));
        }
        uint32_t bhi[2][4], blo[2][4];
        #pragma unroll
        for (int nb = 0; nb < 2; nb++) {
            uint32_t addr = smb + OFF_BHI +
                (uint32_t)((k0 + r8 + (qd & 1) * 8) * PITCH + wn + nb * 16 + (qd >> 1) * 8) * 2;
            LDSM_X4_T(bhi[nb], addr);
            LDSM_X4_T(blo[nb], addr + (OFF_BLO - OFF_BHI));
        }
        #pragma unroll
        for (int mt = 0; mt < 4; mt++)
            #pragma unroll
            for (int nt = 0; nt < 4; nt++) {
                const int nb = nt >> 1, p = (nt & 1) * 2;
                MMA_BF16(c[mt][nt], ahi[mt], bhi[nb][p], bhi[nb][p + 1]);
                MMA_BF16(c[mt][nt], ahi[mt], blo[nb][p], blo[nb][p + 1]);
                MMA_BF16(c[mt][nt], alo[mt], bhi[nb][p], bhi[nb][p + 1]);
            }
    }

    // ---------------- epilogue: e[n] = sum_d v[d]*tanh(M[d][n]) ------------
    // frag map: c[mt][nt][{0,1,2,3}] = M[wm+mt*16+g(+8)][wn+nt*8+tq*2(+1)]
    {
        const int g = lane >> 2, tq = lane & 3;
        #pragma unroll
        for (int nt = 0; nt < 4; nt++) {
            #pragma unroll
            for (int j = 0; j < 2; j++) {
                float s = 0.f;
                #pragma unroll
                for (int mt = 0; mt < 4; mt++) {
                    int d0 = wm + mt * 16 + g;
                    s += sv[d0]     * ftanh(c[mt][nt][j]);
                    s += sv[d0 + 8] * ftanh(c[mt][nt][2 + j]);
                }
                s += __shfl_xor_sync(0xffffffffu, s, 4);
                s += __shfl_xor_sync(0xffffffffu, s, 8);
                s += __shfl_xor_sync(0xffffffffu, s, 16);
                if (g == 0)
                    ep2[(wid & 1) * 128 + wn + nt * 8 + tq * 2 + j] = s;
            }
        }
    }
    __syncthreads();
    if (tid < 128)
        g_e[b * NL + t * NTILE + tid] = ep2[tid] + ep2[128 + tid];
}

// ---------------------------------------------------------------------------
// Kernel 2: stable softmax per batch
// ---------------------------------------------------------------------------
__global__ __launch_bounds__(TPB) void k2_softmax()
{
    __shared__ float red[TPB];
    const int b = blockIdx.x, tid = threadIdx.x;
    float vals[8];
    float vmax = -1e30f;
    #pragma unroll
    for (int j = 0; j < 8; j++) {
        vals[j] = g_e[b * NL + tid + TPB * j];
        vmax = fmaxf(vmax, vals[j]);
    }
    red[tid] = vmax; __syncthreads();
    for (int off = 128; off > 0; off >>= 1) {
        if (tid < off) red[tid] = fmaxf(red[tid], red[tid + off]);
        __syncthreads();
    }
    vmax = red[0]; __syncthreads();
    float ssum = 0.f;
    #pragma unroll
    for (int j = 0; j < 8; j++) { vals[j] = __expf(vals[j] - vmax); ssum += vals[j]; }
    red[tid] = ssum; __syncthreads();
    for (int off = 128; off > 0; off >>= 1) {
        if (tid < off) red[tid] += red[tid + off];
        __syncthreads();
    }
    float inv = __fdividef(1.f, red[0]);
    #pragma unroll
    for (int j = 0; j < 8; j++) g_w[b * NL + tid + TPB * j] = vals[j] * inv;
}

// ---------------------------------------------------------------------------
// Kernel 3: ctx[b][d] = sum_n w[b][n] * H[b][d][n]   (DRAM-bound GEMV)
// ---------------------------------------------------------------------------
__global__ __launch_bounds__(TPB, 4) void k3_ctx(float* __restrict__ out)
{
    __shared__ float sw_[NL];
    const int tid = threadIdx.x;
    const int dc = blockIdx.x, b = blockIdx.y;

    const float4* Wg = (const float4*)(g_w + b * NL);
    float4* Ws = (float4*)sw_;
    #pragma unroll
    for (int i = tid; i < NL / 4; i += TPB) Ws[i] = Wg[i];
    __syncthreads();

    const int dl = tid >> 3, hh = tid & 7;
    const int d = dc * 32 + dl;
    const float4* Hp = (const float4*)(g_H + (size_t)(b * DDIM + d) * NL);
    float s = 0.f;
    #pragma unroll 8
    for (int j = 0; j < 64; j++) {
        int n4 = hh + j * 8;
        float4 hv = Hp[n4];
        float4 wv = Ws[n4];
        s += hv.x * wv.x + hv.y * wv.y + hv.z * wv.z + hv.w * wv.w;
    }
    #pragma unroll
    for (int off = 4; off > 0; off >>= 1) s += __shfl_down_sync(0xffffffffu, s, off, 8);
    if (hh == 0) out[b * DDIM + d] = s;
}

// ---------------------------------------------------------------------------
extern "C" void kernel_launch(void* const* d_in, const int* in_sizes, int n_in,
                              void* d_out, int out_size)
{
    const int*   seq = (const int*)d_in[0];
    const float* emb = (const float*)d_in[1];
    const float* cw  = (const float*)d_in[2];
    const float* cb  = (const float*)d_in[3];
    const float* Wa  = (const float*)d_in[4];
    const float* va  = (const float*)d_in[5];
    float* out = (float*)d_out;

    cudaFuncSetAttribute(k1_conv_attn, cudaFuncAttributeMaxDynamicSharedMemorySize, SM1_BYTES);

    k1_conv_attn<<<dim3(NT, BATCH), TPB, SM1_BYTES>>>(seq, emb, cw, cb, Wa, va);
    k2_softmax<<<BATCH, TPB>>>();
    k3_ctx<<<dim3(SEC, BATCH), TPB>>>(out);
}

// round 7
// speedup vs baseline: 2.4861x; 1.1157x over previous
#include <cuda_runtime.h>
#include <cuda_bf16.h>
#include <cstdint>

#define BATCH 128
#define SEQLEN 8194
#define NCH 32
#define SEC 4
#define DDIM 128
#define NL 2048
#define NTILE 128
#define NT (NL / NTILE)
#define TPB 512
#define PITCH 136   // bf16 elements per smem row (128 + 8 pad)

// scratch
__device__ float g_e[BATCH * NL];
__device__ float g_w[BATCH * NL];
__device__ float g_H[(size_t)BATCH * DDIM * NL];        // 134 MB fp32 H
__device__ __nv_bfloat16 g_Whi[DDIM * PITCH];           // pre-pitched W_a hi
__device__ __nv_bfloat16 g_Wlo[DDIM * PITCH];           // pre-pitched W_a lo

// ---------------- helpers ----------------
__device__ __forceinline__ uint32_t smem_u32(const void* p) {
    uint32_t a;
    asm("{ .reg .u64 t; cvta.to.shared.u64 t, %1; cvt.u32.u64 %0, t; }" : "=r"(a) : "l"(p));
    return a;
}

#define LDSM_X4(r, addr) \
    asm volatile("ldmatrix.sync.aligned.m8n8.x4.shared.b16 {%0,%1,%2,%3}, [%4];" \
        : "=r"((r)[0]), "=r"((r)[1]), "=r"((r)[2]), "=r"((r)[3]) : "r"(addr))

#define LDSM_X4_T(r, addr) \
    asm volatile("ldmatrix.sync.aligned.m8n8.x4.trans.shared.b16 {%0,%1,%2,%3}, [%4];" \
        : "=r"((r)[0]), "=r"((r)[1]), "=r"((r)[2]), "=r"((r)[3]) : "r"(addr))

#define MMA_BF16(c, a, b0, b1) \
    asm volatile("mma.sync.aligned.m16n8k16.row.col.f32.bf16.bf16.f32 " \
        "{%0,%1,%2,%3}, {%4,%5,%6,%7}, {%8,%9}, {%0,%1,%2,%3};" \
        : "+f"((c)[0]), "+f"((c)[1]), "+f"((c)[2]), "+f"((c)[3]) \
        : "r"((a)[0]), "r"((a)[1]), "r"((a)[2]), "r"((a)[3]), "r"(b0), "r"(b1))

__device__ __forceinline__ float ftanh(float x) {
    float cx = fminf(fmaxf(x, -15.f), 15.f);
    float u = __expf(2.f * cx);
    return __fdividef(u - 1.f, u + 1.f);
}

// SMEM byte offsets (k1): A/B tiles are [128][PITCH] bf16 = 34816 B each
#define OFF_AHI 0
#define OFF_ALO 34816
#define OFF_BHI 69632
#define OFF_BLO 104448
#define OFF_XS   139264              // 2600 floats
#define OFF_SEMB (OFF_XS + 10400)    // 130 f
#define OFF_SCW  (OFF_SEMB + 520)    // 480 f
#define OFF_SCB  (OFF_SCW + 1920)    // 32 f
#define OFF_SV   (OFF_SCB + 128)     // 128 f
#define OFF_SSEQ (OFF_SV + 512)      // 520 i
#define OFF_EP   (OFF_SSEQ + 2080)   // 4 x 128 f
#define SM1_BYTES (OFF_EP + 2048)

// ---------------------------------------------------------------------------
// Kernel 0: one-time W_a -> bf16 hi/lo, pre-pitched [128][136]
// ---------------------------------------------------------------------------
__global__ __launch_bounds__(256) void k0_prep(const float* __restrict__ Wa)
{
    int i = blockIdx.x * 256 + threadIdx.x;
    if (i < DDIM * DDIM) {
        float v = Wa[i];
        __nv_bfloat16 h = __float2bfloat16(v);
        __nv_bfloat16 l = __float2bfloat16(v - __bfloat162float(h));
        int d = i >> 7, e = i & 127;
        g_Whi[d * PITCH + e] = h;
        g_Wlo[d * PITCH + e] = l;
    }
}

// ---------------------------------------------------------------------------
// Kernel 1: embed+conv -> H (gmem fp32 + smem bf16 hi/lo) -> HMMA GEMM -> e
// 16 warps: 4 (m) x 4 (n), warp tile 32x32
// ---------------------------------------------------------------------------
__global__ __launch_bounds__(TPB, 1) void k1_conv_attn(
    const int* __restrict__ seq, const float* __restrict__ emb,
    const float* __restrict__ cw, const float* __restrict__ cb,
    const float* __restrict__ va)
{
    extern __shared__ char sm[];
    const uint32_t smb = smem_u32(sm);
    float* semb = (float*)(sm + OFF_SEMB);
    float* scw  = (float*)(sm + OFF_SCW);
    float* scb  = (float*)(sm + OFF_SCB);
    float* sv   = (float*)(sm + OFF_SV);
    float* xs   = (float*)(sm + OFF_XS);
    int*   sseq = (int*)(sm + OFF_SSEQ);
    float* ep   = (float*)(sm + OFF_EP);

    const int tid = threadIdx.x;
    const int wid = tid >> 5, lane = tid & 31;
    const int t = blockIdx.x, b = blockIdx.y;

    // A tiles: straight copy of pre-converted, pre-pitched W_a (L2-resident)
    {
        const uint4* Ah = (const uint4*)g_Whi;
        const uint4* Al = (const uint4*)g_Wlo;
        uint4* dAh = (uint4*)(sm + OFF_AHI);
        uint4* dAl = (uint4*)(sm + OFF_ALO);
        #pragma unroll
        for (int i = tid; i < DDIM * PITCH / 8; i += TPB) {
            dAh[i] = Ah[i];
            dAl[i] = Al[i];
        }
    }

    // small tables
    for (int i = tid; i < 130; i += TPB) semb[i] = emb[i];
    for (int i = tid; i < 480; i += TPB) scw[i] = cw[i];
    if (tid < 32)  scb[tid] = cb[tid];
    if (tid < 128) sv[tid] = va[tid];
    for (int i = tid; i < 4 * 130; i += TPB) {
        int s = i / 130, j = i % 130;
        sseq[i] = seq[b * SEQLEN + s * NL + t * NTILE + j];
    }
    __syncthreads();

    // embedding
    for (int i = tid; i < 4 * 130 * 5; i += TPB) {
        int i5 = i % 5, j = i / 5;
        xs[i] = semb[sseq[j] * 5 + i5];
    }
    __syncthreads();

    // conv + relu -> g_H (fp32, coalesced in n) + B tiles [e][n] bf16 hi/lo
    for (int idx = tid; idx < DDIM * NTILE; idx += TPB) {
        int n = idx & 127;
        int c = (idx >> 7) & 31;
        int s = idx >> 12;
        int e = c * 4 + s;
        const float* w = scw + c * 15;
        const float* xb = xs + (s * 130 + n) * 5;
        float acc = scb[c];
        #pragma unroll
        for (int k = 0; k < 3; k++)
            #pragma unroll
            for (int i2 = 0; i2 < 5; i2++)
                acc += xb[k * 5 + i2] * w[i2 * 3 + k];
        acc = fmaxf(acc, 0.f);
        g_H[(size_t)(b * DDIM + e) * NL + t * NTILE + n] = acc;
        __nv_bfloat16 hi = __float2bfloat16(acc);
        __nv_bfloat16 lo = __float2bfloat16(acc - __bfloat162float(hi));
        uint32_t o = (uint32_t)(e * PITCH + n) * 2;
        *(__nv_bfloat16*)(sm + OFF_BHI + o) = hi;
        *(__nv_bfloat16*)(sm + OFF_BLO + o) = lo;
    }
    __syncthreads();

    // ---------------- GEMM: M[d][n] = Wa @ H, bf16 hi/lo x3, fp32 accum ----
    // warp layout: 4 (m) x 4 (n); warp tile 32(m) x 32(n)
    const int wm = (wid & 3) * 32;
    const int wn = (wid >> 2) * 32;
    const int qd = lane >> 3, r8 = lane & 7;  // ldmatrix quad / row

    float c[2][4][4];
    #pragma unroll
    for (int mt = 0; mt < 2; mt++)
        #pragma unroll
        for (int nt = 0; nt < 4; nt++)
            #pragma unroll
            for (int q = 0; q < 4; q++) c[mt][nt][q] = 0.f;

    #pragma unroll
    for (int ks = 0; ks < 8; ks++) {
        const int k0 = ks * 16;
        uint32_t ahi[2][4], alo[2][4];
        #pragma unroll
        for (int mt = 0; mt < 2; mt++) {
            uint32_t addr = smb + OFF_AHI +
                (uint32_t)((wm + mt * 16 + r8 + (qd & 1) * 8) * PITCH + k0 + (qd >> 1) * 8) * 2;
            LDSM_X4(ahi[mt], addr);
            LDSM_X4(alo[mt], addr + (OFF_ALO - OFF_AHI));
        }
        uint32_t bhi[2][4], blo[2][4];
        #pragma unroll
        for (int nb = 0; nb < 2; nb++) {
            uint32_t addr = smb + OFF_BHI +
                (uint32_t)((k0 + r8 + (qd & 1) * 8) * PITCH + wn + nb * 16 + (qd >> 1) * 8) * 2;
            LDSM_X4_T(bhi[nb], addr);
            LDSM_X4_T(blo[nb], addr + (OFF_BLO - OFF_BHI));
        }
        #pragma unroll
        for (int mt = 0; mt < 2; mt++)
            #pragma unroll
            for (int nt = 0; nt < 4; nt++) {
                const int nb = nt >> 1, p = (nt & 1) * 2;
                MMA_BF16(c[mt][nt], ahi[mt], bhi[nb][p], bhi[nb][p + 1]);
                MMA_BF16(c[mt][nt], ahi[mt], blo[nb][p], blo[nb][p + 1]);
                MMA_BF16(c[mt][nt], alo[mt], bhi[nb][p], bhi[nb][p + 1]);
            }
    }

    // ---------------- epilogue: e[n] = sum_d v[d]*tanh(M[d][n]) ------------
    // frag map: c[mt][nt][{0,1,2,3}] = M[wm+mt*16+g(+8)][wn+nt*8+tq*2(+1)]
    {
        const int g = lane >> 2, tq = lane & 3;
        #pragma unroll
        for (int nt = 0; nt < 4; nt++) {
            #pragma unroll
            for (int j = 0; j < 2; j++) {
                float s = 0.f;
                #pragma unroll
                for (int mt = 0; mt < 2; mt++) {
                    int d0 = wm + mt * 16 + g;
                    s += sv[d0]     * ftanh(c[mt][nt][j]);
                    s += sv[d0 + 8] * ftanh(c[mt][nt][2 + j]);
                }
                s += __shfl_xor_sync(0xffffffffu, s, 4);
                s += __shfl_xor_sync(0xffffffffu, s, 8);
                s += __shfl_xor_sync(0xffffffffu, s, 16);
                if (g == 0)
                    ep[(wid & 3) * 128 + wn + nt * 8 + tq * 2 + j] = s;
            }
        }
    }
    __syncthreads();
    if (tid < 128)
        g_e[b * NL + t * NTILE + tid] =
            (ep[tid] + ep[128 + tid]) + (ep[256 + tid] + ep[384 + tid]);
}

// ---------------------------------------------------------------------------
// Kernel 2: stable softmax per batch
// ---------------------------------------------------------------------------
__global__ __launch_bounds__(256) void k2_softmax()
{
    __shared__ float red[256];
    const int b = blockIdx.x, tid = threadIdx.x;
    float vals[8];
    float vmax = -1e30f;
    #pragma unroll
    for (int j = 0; j < 8; j++) {
        vals[j] = g_e[b * NL + tid + 256 * j];
        vmax = fmaxf(vmax, vals[j]);
    }
    red[tid] = vmax; __syncthreads();
    for (int off = 128; off > 0; off >>= 1) {
        if (tid < off) red[tid] = fmaxf(red[tid], red[tid + off]);
        __syncthreads();
    }
    vmax = red[0]; __syncthreads();
    float ssum = 0.f;
    #pragma unroll
    for (int j = 0; j < 8; j++) { vals[j] = __expf(vals[j] - vmax); ssum += vals[j]; }
    red[tid] = ssum; __syncthreads();
    for (int off = 128; off > 0; off >>= 1) {
        if (tid < off) red[tid] += red[tid + off];
        __syncthreads();
    }
    float inv = __fdividef(1.f, red[0]);
    #pragma unroll
    for (int j = 0; j < 8; j++) g_w[b * NL + tid + 256 * j] = vals[j] * inv;
}

// ---------------------------------------------------------------------------
// Kernel 3: ctx[b][d] = sum_n w[b][n] * H[b][d][n]   (DRAM-bound GEMV)
// ---------------------------------------------------------------------------
__global__ __launch_bounds__(256, 4) void k3_ctx(float* __restrict__ out)
{
    __shared__ float sw_[NL];
    const int tid = threadIdx.x;
    const int dc = blockIdx.x, b = blockIdx.y;

    const float4* Wg = (const float4*)(g_w + b * NL);
    float4* Ws = (float4*)sw_;
    #pragma unroll
    for (int i = tid; i < NL / 4; i += 256) Ws[i] = Wg[i];
    __syncthreads();

    const int dl = tid >> 3, hh = tid & 7;
    const int d = dc * 32 + dl;
    const float4* Hp = (const float4*)(g_H + (size_t)(b * DDIM + d) * NL);
    float s = 0.f;
    #pragma unroll 8
    for (int j = 0; j < 64; j++) {
        int n4 = hh + j * 8;
        float4 hv = Hp[n4];
        float4 wv = Ws[n4];
        s += hv.x * wv.x + hv.y * wv.y + hv.z * wv.z + hv.w * wv.w;
    }
    #pragma unroll
    for (int off = 4; off > 0; off >>= 1) s += __shfl_down_sync(0xffffffffu, s, off, 8);
    if (hh == 0) out[b * DDIM + d] = s;
}

// ---------------------------------------------------------------------------
extern "C" void kernel_launch(void* const* d_in, const int* in_sizes, int n_in,
                              void* d_out, int out_size)
{
    const int*   seq = (const int*)d_in[0];
    const float* emb = (const float*)d_in[1];
    const float* cw  = (const float*)d_in[2];
    const float* cb  = (const float*)d_in[3];
    const float* Wa  = (const float*)d_in[4];
    const float* va  = (const float*)d_in[5];
    float* out = (float*)d_out;

    cudaFuncSetAttribute(k1_conv_attn, cudaFuncAttributeMaxDynamicSharedMemorySize, SM1_BYTES);

    k0_prep<<<(DDIM * DDIM + 255) / 256, 256>>>(Wa);
    k1_conv_attn<<<dim3(NT, BATCH), TPB, SM1_BYTES>>>(seq, emb, cw, cb, va);
    k2_softmax<<<BATCH, 256>>>();
    k3_ctx<<<dim3(SEC, BATCH), 256>>>(out);
}

// round 9
// speedup vs baseline: 3.7448x; 1.5063x over previous
#include <cuda_runtime.h>
#include <cuda_bf16.h>
#include <cstdint>

#define BATCH 128
#define SEQLEN 8194
#define NCH 32
#define SEC 4
#define DDIM 128
#define NL 2048
#define NTILE 128
#define NT (NL / NTILE)
#define TPB 512
#define PITCH 136   // bf16 elements per smem row (128 + 8 pad)
#define PSTRIDE 32  // padded letter stride in P LUT (bank-conflict-free)

// scratch
__device__ float g_e[BATCH * NL];
__device__ float g_w[BATCH * NL];
__device__ float g_H[(size_t)BATCH * DDIM * NL];        // 134 MB fp32 H
__device__ __nv_bfloat16 g_Whi[DDIM * PITCH];           // pre-pitched W_a hi
__device__ __nv_bfloat16 g_Wlo[DDIM * PITCH];           // pre-pitched W_a lo
__device__ float g_P[NCH * 3 * PSTRIDE];                // conv letter LUT

// ---------------- helpers ----------------
__device__ __forceinline__ uint32_t smem_u32(const void* p) {
    uint32_t a;
    asm("{ .reg .u64 t; cvta.to.shared.u64 t, %1; cvt.u32.u64 %0, t; }" : "=r"(a) : "l"(p));
    return a;
}

#define LDSM_X4(r, addr) \
    asm volatile("ldmatrix.sync.aligned.m8n8.x4.shared.b16 {%0,%1,%2,%3}, [%4];" \
        : "=r"((r)[0]), "=r"((r)[1]), "=r"((r)[2]), "=r"((r)[3]) : "r"(addr))

#define LDSM_X4_T(r, addr) \
    asm volatile("ldmatrix.sync.aligned.m8n8.x4.trans.shared.b16 {%0,%1,%2,%3}, [%4];" \
        : "=r"((r)[0]), "=r"((r)[1]), "=r"((r)[2]), "=r"((r)[3]) : "r"(addr))

#define MMA_BF16(c, a, b0, b1) \
    asm volatile("mma.sync.aligned.m16n8k16.row.col.f32.bf16.bf16.f32 " \
        "{%0,%1,%2,%3}, {%4,%5,%6,%7}, {%8,%9}, {%0,%1,%2,%3};" \
        : "+f"((c)[0]), "+f"((c)[1]), "+f"((c)[2]), "+f"((c)[3]) \
        : "r"((a)[0]), "r"((a)[1]), "r"((a)[2]), "r"((a)[3]), "r"(b0), "r"(b1))

__device__ __forceinline__ float ftanh(float x) {
    float r;
    asm("tanh.approx.f32 %0, %1;" : "=f"(r) : "f"(x));
    return r;
}

// SMEM byte offsets (k1): A/B tiles are [128][PITCH] bf16 = 34816 B each
#define OFF_AHI 0
#define OFF_ALO 34816
#define OFF_BHI 69632
#define OFF_BLO 104448
#define OFF_SP   139264              // P LUT: 3072 f = 12288 B
#define OFF_SCB  (OFF_SP + 12288)    // 32 f
#define OFF_SV   (OFF_SCB + 128)     // 128 f
#define OFF_SSEQ (OFF_SV + 512)      // 520 i
#define OFF_EP   (OFF_SSEQ + 2080)   // 4 x 128 f
#define SM1_BYTES (OFF_EP + 2048)

// ---------------------------------------------------------------------------
// Kernel 0: one-time prep: W_a -> bf16 hi/lo pre-pitched; conv letter LUT
//   P[c][k][l] = sum_i emb[l*5+i] * cw[c*15 + i*3 + k]
// ---------------------------------------------------------------------------
__global__ __launch_bounds__(256) void k0_prep(
    const float* __restrict__ Wa, const float* __restrict__ emb,
    const float* __restrict__ cw)
{
    int i = blockIdx.x * 256 + threadIdx.x;
    if (i < DDIM * DDIM) {
        float v = Wa[i];
        __nv_bfloat16 h = __float2bfloat16(v);
        __nv_bfloat16 l = __float2bfloat16(v - __bfloat162float(h));
        int d = i >> 7, e = i & 127;
        g_Whi[d * PITCH + e] = h;
        g_Wlo[d * PITCH + e] = l;
    }
    int j = i - DDIM * DDIM;
    if (j >= 0 && j < NCH * 3 * 26) {
        int c = j / (3 * 26), k = (j / 26) % 3, l = j % 26;
        float s = 0.f;
        #pragma unroll
        for (int i2 = 0; i2 < 5; i2++)
            s += emb[l * 5 + i2] * cw[c * 15 + i2 * 3 + k];
        g_P[(c * 3 + k) * PSTRIDE + l] = s;
    }
}

// ---------------------------------------------------------------------------
// Kernel 1: LUT-conv -> H (gmem fp32 + smem bf16 hi/lo) -> HMMA GEMM -> e
// 16 warps: 4 (m) x 4 (n), warp tile 32x32
// ---------------------------------------------------------------------------
__global__ __launch_bounds__(TPB, 1) void k1_conv_attn(
    const int* __restrict__ seq, const float* __restrict__ cb,
    const float* __restrict__ va)
{
    extern __shared__ char sm[];
    const uint32_t smb = smem_u32(sm);
    float* sP   = (float*)(sm + OFF_SP);
    float* scb  = (float*)(sm + OFF_SCB);
    float* sv   = (float*)(sm + OFF_SV);
    int*   sseq = (int*)(sm + OFF_SSEQ);
    float* ep   = (float*)(sm + OFF_EP);

    const int tid = threadIdx.x;
    const int wid = tid >> 5, lane = tid & 31;
    const int t = blockIdx.x, b = blockIdx.y;

    // A tiles: straight copy of pre-converted, pre-pitched W_a (L2-resident)
    {
        const uint4* Ah = (const uint4*)g_Whi;
        const uint4* Al = (const uint4*)g_Wlo;
        uint4* dAh = (uint4*)(sm + OFF_AHI);
        uint4* dAl = (uint4*)(sm + OFF_ALO);
        #pragma unroll
        for (int i = tid; i < DDIM * PITCH / 8; i += TPB) {
            dAh[i] = Ah[i];
            dAl[i] = Al[i];
        }
    }

    // small tables
    for (int i = tid; i < NCH * 3 * PSTRIDE; i += TPB) sP[i] = g_P[i];
    if (tid < 32)  scb[tid] = cb[tid];
    if (tid < 128) sv[tid] = va[tid];
    for (int i = tid; i < 4 * 130; i += TPB) {
        int s = i / 130, j = i % 130;
        sseq[i] = seq[b * SEQLEN + s * NL + t * NTILE + j];
    }
    __syncthreads();

    // conv via LUT + relu -> g_H (fp32, coalesced in n) + B tiles bf16 hi/lo
    {
        const int n = tid & 127;
        const int cs0 = tid >> 7;   // 0..3
        float* Hbase = g_H + (size_t)b * DDIM * NL + (size_t)t * NTILE + n;
        #pragma unroll
        for (int s = 0; s < 4; s++) {
            const int l0 = sseq[s * 130 + n];
            const int l1 = sseq[s * 130 + n + 1];
            const int l2 = sseq[s * 130 + n + 2];
            #pragma unroll
            for (int jj = 0; jj < 8; jj++) {
                const int c = cs0 + 4 * jj;
                const float* Pc = sP + c * 3 * PSTRIDE;
                float acc = scb[c] + Pc[l0] + Pc[PSTRIDE + l1] + Pc[2 * PSTRIDE + l2];
                acc = fmaxf(acc, 0.f);
                const int e = c * 4 + s;
                Hbase[(size_t)e * NL] = acc;
                __nv_bfloat16 hi = __float2bfloat16(acc);
                __nv_bfloat16 lo = __float2bfloat16(acc - __bfloat162float(hi));
                uint32_t o = (uint32_t)(e * PITCH + n) * 2;
                *(__nv_bfloat16*)(sm + OFF_BHI + o) = hi;
                *(__nv_bfloat16*)(sm + OFF_BLO + o) = lo;
            }
        }
    }
    __syncthreads();

    // ---------------- GEMM: M[d][n] = Wa @ H, bf16 hi/lo x3, fp32 accum ----
    const int wm = (wid & 3) * 32;
    const int wn = (wid >> 2) * 32;
    const int qd = lane >> 3, r8 = lane & 7;

    float c[2][4][4];
    #pragma unroll
    for (int mt = 0; mt < 2; mt++)
        #pragma unroll
        for (int nt = 0; nt < 4; nt++)
            #pragma unroll
            for (int q = 0; q < 4; q++) c[mt][nt][q] = 0.f;

    #pragma unroll
    for (int ks = 0; ks < 8; ks++) {
        const int k0 = ks * 16;
        uint32_t ahi[2][4], alo[2][4];
        #pragma unroll
        for (int mt = 0; mt < 2; mt++) {
            uint32_t addr = smb + OFF_AHI +
                (uint32_t)((wm + mt * 16 + r8 + (qd & 1) * 8) * PITCH + k0 + (qd >> 1) * 8) * 2;
            LDSM_X4(ahi[mt], addr);
            LDSM_X4(alo[mt], addr + (OFF_ALO - OFF_AHI));
        }
        uint32_t bhi[2][4], blo[2][4];
        #pragma unroll
        for (int nb = 0; nb < 2; nb++) {
            uint32_t addr = smb + OFF_BHI +
                (uint32_t)((k0 + r8 + (qd & 1) * 8) * PITCH + wn + nb * 16 + (qd >> 1) * 8) * 2;
            LDSM_X4_T(bhi[nb], addr);
            LDSM_X4_T(blo[nb], addr + (OFF_BLO - OFF_BHI));
        }
        #pragma unroll
        for (int mt = 0; mt < 2; mt++)
            #pragma unroll
            for (int nt = 0; nt < 4; nt++) {
                const int nb = nt >> 1, p = (nt & 1) * 2;
                MMA_BF16(c[mt][nt], ahi[mt], bhi[nb][p], bhi[nb][p + 1]);
                MMA_BF16(c[mt][nt], ahi[mt], blo[nb][p], blo[nb][p + 1]);
                MMA_BF16(c[mt][nt], alo[mt], bhi[nb][p], bhi[nb][p + 1]);
            }
    }

    // ---------------- epilogue: e[n] = sum_d v[d]*tanh(M[d][n]) ------------
    {
        const int g = lane >> 2, tq = lane & 3;
        #pragma unroll
        for (int nt = 0; nt < 4; nt++) {
            #pragma unroll
            for (int j = 0; j < 2; j++) {
                float s = 0.f;
                #pragma unroll
                for (int mt = 0; mt < 2; mt++) {
                    int d0 = wm + mt * 16 + g;
                    s += sv[d0]     * ftanh(c[mt][nt][j]);
                    s += sv[d0 + 8] * ftanh(c[mt][nt][2 + j]);
                }
                s += __shfl_xor_sync(0xffffffffu, s, 4);
                s += __shfl_xor_sync(0xffffffffu, s, 8);
                s += __shfl_xor_sync(0xffffffffu, s, 16);
                if (g == 0)
                    ep[(wid & 3) * 128 + wn + nt * 8 + tq * 2 + j] = s;
            }
        }
    }
    __syncthreads();
    if (tid < 128)
        g_e[b * NL + t * NTILE + tid] =
            (ep[tid] + ep[128 + tid]) + (ep[256 + tid] + ep[384 + tid]);
}

// ---------------------------------------------------------------------------
// Kernel 2: stable softmax per batch
// ---------------------------------------------------------------------------
__global__ __launch_bounds__(256) void k2_softmax()
{
    __shared__ float red[256];
    const int b = blockIdx.x, tid = threadIdx.x;
    float vals[8];
    float vmax = -1e30f;
    #pragma unroll
    for (int j = 0; j < 8; j++) {
        vals[j] = g_e[b * NL + tid + 256 * j];
        vmax = fmaxf(vmax, vals[j]);
    }
    red[tid] = vmax; __syncthreads();
    for (int off = 128; off > 0; off >>= 1) {
        if (tid < off) red[tid] = fmaxf(red[tid], red[tid + off]);
        __syncthreads();
    }
    vmax = red[0]; __syncthreads();
    float ssum = 0.f;
    #pragma unroll
    for (int j = 0; j < 8; j++) { vals[j] = __expf(vals[j] - vmax); ssum += vals[j]; }
    red[tid] = ssum; __syncthreads();
    for (int off = 128; off > 0; off >>= 1) {
        if (tid < off) red[tid] += red[tid + off];
        __syncthreads();
    }
    float inv = __fdividef(1.f, red[0]);
    #pragma unroll
    for (int j = 0; j < 8; j++) g_w[b * NL + tid + 256 * j] = vals[j] * inv;
}

// ---------------------------------------------------------------------------
// Kernel 3: ctx[b][d] = sum_n w[b][n] * H[b][d][n]   (DRAM-bound GEMV)
// grid (8, BATCH): 16 d-rows per CTA for residency
// ---------------------------------------------------------------------------
__global__ __launch_bounds__(256, 4) void k3_ctx(float* __restrict__ out)
{
    __shared__ float sw_[NL];
    const int tid = threadIdx.x;
    const int dc = blockIdx.x, b = blockIdx.y;

    const float4* Wg = (const float4*)(g_w + b * NL);
    float4* Ws = (float4*)sw_;
    #pragma unroll
    for (int i = tid; i < NL / 4; i += 256) Ws[i] = Wg[i];
    __syncthreads();

    const int dl = tid >> 4, hh = tid & 15;
    const int d = dc * 16 + dl;
    const float4* Hp = (const float4*)(g_H + (size_t)(b * DDIM + d) * NL);
    float s = 0.f;
    #pragma unroll 8
    for (int j = 0; j < 32; j++) {
        int n4 = hh + j * 16;
        float4 hv = Hp[n4];
        float4 wv = Ws[n4];
        s += hv.x * wv.x + hv.y * wv.y + hv.z * wv.z + hv.w * wv.w;
    }
    #pragma unroll
    for (int off = 8; off > 0; off >>= 1) s += __shfl_down_sync(0xffffffffu, s, off, 16);
    if (hh == 0) out[b * DDIM + d] = s;
}

// ---------------------------------------------------------------------------
extern "C" void kernel_launch(void* const* d_in, const int* in_sizes, int n_in,
                              void* d_out, int out_size)
{
    const int*   seq = (const int*)d_in[0];
    const float* emb = (const float*)d_in[1];
    const float* cw  = (const float*)d_in[2];
    const float* cb  = (const float*)d_in[3];
    const float* Wa  = (const float*)d_in[4];
    const float* va  = (const float*)d_in[5];
    float* out = (float*)d_out;

    cudaFuncSetAttribute(k1_conv_attn, cudaFuncAttributeMaxDynamicSharedMemorySize, SM1_BYTES);

    k0_prep<<<(DDIM * DDIM + NCH * 3 * 26 + 255) / 256, 256>>>(Wa, emb, cw);
    k1_conv_attn<<<dim3(NT, BATCH), TPB, SM1_BYTES>>>(seq, cb, va);
    k2_softmax<<<BATCH, 256>>>();
    k3_ctx<<<dim3(8, BATCH), 256>>>(out);
}

// round 11
// speedup vs baseline: 4.3998x; 1.1749x over previous
#include <cuda_runtime.h>
#include <cuda_bf16.h>
#include <cstdint>

#define BATCH 128
#define SEQLEN 8194
#define NCH 32
#define SEC 4
#define DDIM 128
#define NL 2048
#define NTILE 128
#define NT (NL / NTILE)
#define TPB 512
#define PITCH 136   // bf16 elements per smem row (128 + 8 pad)
#define PSTRIDE 32  // padded letter stride in P LUT

// scratch
__device__ float g_e[BATCH * NL];
__device__ float g_w[BATCH * NL];
__device__ float g_H[(size_t)BATCH * DDIM * NL];        // 134 MB fp32 H
__device__ __nv_bfloat16 g_Whi[DDIM * PITCH];           // pre-pitched W_a hi
__device__ __nv_bfloat16 g_Wlo[DDIM * PITCH];           // pre-pitched W_a lo
__device__ float g_P[NCH * 3 * PSTRIDE];                // conv letter LUT (bias folded)

// ---------------- helpers ----------------
__device__ __forceinline__ uint32_t smem_u32(const void* p) {
    uint32_t a;
    asm("{ .reg .u64 t; cvta.to.shared.u64 t, %1; cvt.u32.u64 %0, t; }" : "=r"(a) : "l"(p));
    return a;
}

#define LDSM_X4(r, addr) \
    asm volatile("ldmatrix.sync.aligned.m8n8.x4.shared.b16 {%0,%1,%2,%3}, [%4];" \
        : "=r"((r)[0]), "=r"((r)[1]), "=r"((r)[2]), "=r"((r)[3]) : "r"(addr))

#define LDSM_X4_T(r, addr) \
    asm volatile("ldmatrix.sync.aligned.m8n8.x4.trans.shared.b16 {%0,%1,%2,%3}, [%4];" \
        : "=r"((r)[0]), "=r"((r)[1]), "=r"((r)[2]), "=r"((r)[3]) : "r"(addr))

#define MMA_BF16(c, a, b0, b1) \
    asm volatile("mma.sync.aligned.m16n8k16.row.col.f32.bf16.bf16.f32 " \
        "{%0,%1,%2,%3}, {%4,%5,%6,%7}, {%8,%9}, {%0,%1,%2,%3};" \
        : "+f"((c)[0]), "+f"((c)[1]), "+f"((c)[2]), "+f"((c)[3]) \
        : "r"((a)[0]), "r"((a)[1]), "r"((a)[2]), "r"((a)[3]), "r"(b0), "r"(b1))

__device__ __forceinline__ float ftanh(float x) {
    float r;
    asm("tanh.approx.f32 %0, %1;" : "=f"(r) : "f"(x));
    return r;
}

// SMEM byte offsets (k1): tiles are [128][PITCH] bf16 = 34816 B each
#define OFF_AHI 0
#define OFF_ALO 34816
#define OFF_BHI 69632
#define OFF_SP   104448              // P LUT: 3072 f = 12288 B
#define OFF_SV   (OFF_SP + 12288)    // 128 f
#define OFF_SSEQ (OFF_SV + 512)      // 520 i
#define OFF_EP   (OFF_SSEQ + 2080)   // 4 x 128 f
#define SM1_BYTES (OFF_EP + 2048)

// ---------------------------------------------------------------------------
// Kernel 0: one-time prep: W_a -> bf16 hi/lo pre-pitched; conv LUT w/ bias
//   P[c][k][l] = sum_i emb[l*5+i] * cw[c*15 + i*3 + k]  (+ cb[c] at k==0)
// ---------------------------------------------------------------------------
__global__ __launch_bounds__(256) void k0_prep(
    const float* __restrict__ Wa, const float* __restrict__ emb,
    const float* __restrict__ cw, const float* __restrict__ cb)
{
    int i = blockIdx.x * 256 + threadIdx.x;
    if (i < DDIM * DDIM) {
        float v = Wa[i];
        __nv_bfloat16 h = __float2bfloat16(v);
        __nv_bfloat16 l = __float2bfloat16(v - __bfloat162float(h));
        int d = i >> 7, e = i & 127;
        g_Whi[d * PITCH + e] = h;
        g_Wlo[d * PITCH + e] = l;
    }
    int j = i - DDIM * DDIM;
    if (j >= 0 && j < NCH * 3 * 26) {
        int c = j / (3 * 26), k = (j / 26) % 3, l = j % 26;
        float s = (k == 0) ? cb[c] : 0.f;
        #pragma unroll
        for (int i2 = 0; i2 < 5; i2++)
            s += emb[l * 5 + i2] * cw[c * 15 + i2 * 3 + k];
        g_P[(c * 3 + k) * PSTRIDE + l] = s;
    }
}

// ---------------------------------------------------------------------------
// Kernel 1: LUT-conv -> H (gmem fp32 + smem bf16 hi) -> HMMA GEMM (2-term) -> e
// 16 warps: 4 (m) x 4 (n), warp tile 32x32
// ---------------------------------------------------------------------------
__global__ __launch_bounds__(TPB, 1) void k1_conv_attn(
    const int* __restrict__ seq, const float* __restrict__ va)
{
    extern __shared__ char sm[];
    const uint32_t smb = smem_u32(sm);
    float* sP   = (float*)(sm + OFF_SP);
    float* sv   = (float*)(sm + OFF_SV);
    int*   sseq = (int*)(sm + OFF_SSEQ);
    float* ep   = (float*)(sm + OFF_EP);

    const int tid = threadIdx.x;
    const int wid = tid >> 5, lane = tid & 31;
    const int t = blockIdx.x, b = blockIdx.y;

    // A tiles: straight copy of pre-converted, pre-pitched W_a (L2-resident)
    {
        const uint4* Ah = (const uint4*)g_Whi;
        const uint4* Al = (const uint4*)g_Wlo;
        uint4* dAh = (uint4*)(sm + OFF_AHI);
        uint4* dAl = (uint4*)(sm + OFF_ALO);
        #pragma unroll
        for (int i = tid; i < DDIM * PITCH / 8; i += TPB) {
            dAh[i] = Ah[i];
            dAl[i] = Al[i];
        }
    }

    // small tables
    for (int i = tid; i < NCH * 3 * PSTRIDE; i += TPB) sP[i] = g_P[i];
    if (tid < 128) sv[tid] = va[tid];
    for (int i = tid; i < 4 * 130; i += TPB) {
        int s = i / 130, j = i % 130;
        sseq[i] = seq[b * SEQLEN + s * NL + t * NTILE + j];
    }
    __syncthreads();

    // conv via LUT + relu -> g_H (fp32, coalesced in n) + B hi tile (bf16)
    {
        const int n = tid & 127;
        const int cs0 = tid >> 7;   // 0..3
        float* Hbase = g_H + (size_t)b * DDIM * NL + (size_t)t * NTILE + n;
        #pragma unroll
        for (int s = 0; s < 4; s++) {
            const int l0 = sseq[s * 130 + n];
            const int l1 = sseq[s * 130 + n + 1];
            const int l2 = sseq[s * 130 + n + 2];
            #pragma unroll
            for (int jj = 0; jj < 8; jj++) {
                const int c = cs0 + 4 * jj;
                const float* Pc = sP + c * 3 * PSTRIDE;
                float acc = Pc[l0] + Pc[PSTRIDE + l1] + Pc[2 * PSTRIDE + l2];
                acc = fmaxf(acc, 0.f);
                const int e = c * 4 + s;
                Hbase[(size_t)e * NL] = acc;
                uint32_t o = (uint32_t)(e * PITCH + n) * 2;
                *(__nv_bfloat16*)(sm + OFF_BHI + o) = __float2bfloat16(acc);
            }
        }
    }
    __syncthreads();

    // ---------------- GEMM: M[d][n] = (Ahi+Alo) @ Bhi, fp32 accum ----------
    const int wm = (wid & 3) * 32;
    const int wn = (wid >> 2) * 32;
    const int qd = lane >> 3, r8 = lane & 7;

    float c[2][4][4];
    #pragma unroll
    for (int mt = 0; mt < 2; mt++)
        #pragma unroll
        for (int nt = 0; nt < 4; nt++)
            #pragma unroll
            for (int q = 0; q < 4; q++) c[mt][nt][q] = 0.f;

    #pragma unroll
    for (int ks = 0; ks < 8; ks++) {
        const int k0 = ks * 16;
        uint32_t ahi[2][4], alo[2][4];
        #pragma unroll
        for (int mt = 0; mt < 2; mt++) {
            uint32_t addr = smb + OFF_AHI +
                (uint32_t)((wm + mt * 16 + r8 + (qd & 1) * 8) * PITCH + k0 + (qd >> 1) * 8) * 2;
            LDSM_X4(ahi[mt], addr);
            LDSM_X4(alo[mt], addr + (OFF_ALO - OFF_AHI));
        }
        uint32_t bhi[2][4];
        #pragma unroll
        for (int nb = 0; nb < 2; nb++) {
            uint32_t addr = smb + OFF_BHI +
                (uint32_t)((k0 + r8 + (qd & 1) * 8) * PITCH + wn + nb * 16 + (qd >> 1) * 8) * 2;
            LDSM_X4_T(bhi[nb], addr);
        }
        #pragma unroll
        for (int mt = 0; mt < 2; mt++)
            #pragma unroll
            for (int nt = 0; nt < 4; nt++) {
                const int nb = nt >> 1, p = (nt & 1) * 2;
                MMA_BF16(c[mt][nt], ahi[mt], bhi[nb][p], bhi[nb][p + 1]);
                MMA_BF16(c[mt][nt], alo[mt], bhi[nb][p], bhi[nb][p + 1]);
            }
    }

    // ---------------- epilogue: e[n] = sum_d v[d]*tanh(M[d][n]) ------------
    {
        const int g = lane >> 2, tq = lane & 3;
        #pragma unroll
        for (int nt = 0; nt < 4; nt++) {
            #pragma unroll
            for (int j = 0; j < 2; j++) {
                float s = 0.f;
                #pragma unroll
                for (int mt = 0; mt < 2; mt++) {
                    int d0 = wm + mt * 16 + g;
                    s += sv[d0]     * ftanh(c[mt][nt][j]);
                    s += sv[d0 + 8] * ftanh(c[mt][nt][2 + j]);
                }
                s += __shfl_xor_sync(0xffffffffu, s, 4);
                s += __shfl_xor_sync(0xffffffffu, s, 8);
                s += __shfl_xor_sync(0xffffffffu, s, 16);
                if (g == 0)
                    ep[(wid & 3) * 128 + wn + nt * 8 + tq * 2 + j] = s;
            }
        }
    }
    __syncthreads();
    if (tid < 128)
        g_e[b * NL + t * NTILE + tid] =
            (ep[tid] + ep[128 + tid]) + (ep[256 + tid] + ep[384 + tid]);
}

// ---------------------------------------------------------------------------
// Kernel 2: stable softmax per batch
// ---------------------------------------------------------------------------
__global__ __launch_bounds__(256) void k2_softmax()
{
    __shared__ float red[256];
    const int b = blockIdx.x, tid = threadIdx.x;
    float vals[8];
    float vmax = -1e30f;
    #pragma unroll
    for (int j = 0; j < 8; j++) {
        vals[j] = g_e[b * NL + tid + 256 * j];
        vmax = fmaxf(vmax, vals[j]);
    }
    red[tid] = vmax; __syncthreads();
    for (int off = 128; off > 0; off >>= 1) {
        if (tid < off) red[tid] = fmaxf(red[tid], red[tid + off]);
        __syncthreads();
    }
    vmax = red[0]; __syncthreads();
    float ssum = 0.f;
    #pragma unroll
    for (int j = 0; j < 8; j++) { vals[j] = __expf(vals[j] - vmax); ssum += vals[j]; }
    red[tid] = ssum; __syncthreads();
    for (int off = 128; off > 0; off >>= 1) {
        if (tid < off) red[tid] += red[tid + off];
        __syncthreads();
    }
    float inv = __fdividef(1.f, red[0]);
    #pragma unroll
    for (int j = 0; j < 8; j++) g_w[b * NL + tid + 256 * j] = vals[j] * inv;
}

// ---------------------------------------------------------------------------
// Kernel 3: ctx[b][d] = sum_n w[b][n] * H[b][d][n]   (DRAM-bound GEMV)
// grid (16, BATCH): 8 d-rows per CTA, one warp per d-row
// ---------------------------------------------------------------------------
__global__ __launch_bounds__(256, 4) void k3_ctx(float* __restrict__ out)
{
    __shared__ float sw_[NL];
    const int tid = threadIdx.x;
    const int dc = blockIdx.x, b = blockIdx.y;

    const float4* Wg = (const float4*)(g_w + b * NL);
    float4* Ws = (float4*)sw_;
    #pragma unroll
    for (int i = tid; i < NL / 4; i += 256) Ws[i] = Wg[i];
    __syncthreads();

    const int dl = tid >> 5, hh = tid & 31;
    const int d = dc * 8 + dl;
    const float4* Hp = (const float4*)(g_H + (size_t)(b * DDIM + d) * NL);
    float s = 0.f;
    #pragma unroll
    for (int j = 0; j < 16; j++) {
        int n4 = hh + j * 32;
        float4 hv = Hp[n4];
        float4 wv = Ws[n4];
        s += hv.x * wv.x + hv.y * wv.y + hv.z * wv.z + hv.w * wv.w;
    }
    #pragma unroll
    for (int off = 16; off > 0; off >>= 1) s += __shfl_down_sync(0xffffffffu, s, off);
    if (hh == 0) out[b * DDIM + d] = s;
}

// ---------------------------------------------------------------------------
extern "C" void kernel_launch(void* const* d_in, const int* in_sizes, int n_in,
                              void* d_out, int out_size)
{
    const int*   seq = (const int*)d_in[0];
    const float* emb = (const float*)d_in[1];
    const float* cw  = (const float*)d_in[2];
    const float* cb  = (const float*)d_in[3];
    const float* Wa  = (const float*)d_in[4];
    const float* va  = (const float*)d_in[5];
    float* out = (float*)d_out;

    cudaFuncSetAttribute(k1_conv_attn, cudaFuncAttributeMaxDynamicSharedMemorySize, SM1_BYTES);

    k0_prep<<<(DDIM * DDIM + NCH * 3 * 26 + 255) / 256, 256>>>(Wa, emb, cw, cb);
    k1_conv_attn<<<dim3(NT, BATCH), TPB, SM1_BYTES>>>(seq, va);
    k2_softmax<<<BATCH, 256>>>();
    k3_ctx<<<dim3(16, BATCH), 256>>>(out);
}